// round 1
// baseline (speedup 1.0000x reference)
#include <cuda_runtime.h>
#include <cuda_bf16.h>
#include <cstddef>

// ---------------- problem constants ----------------
#define BB   256      // batch
#define PP   100      // pomo / query positions
#define NN   101      // nodes (N+1)
#define EE   256      // embedding
#define HH   16       // heads
#define DD   16       // head dim
#define NE   8        // experts
#define TT   (BB*PP)  // tokens = 25600
#define KQ   260      // E+4 for q projection

// ---------------- scratch (device globals; no allocation) ----------------
__device__ float g_q  [TT      * EE];          // 25600 x 256
__device__ float g_k  [BB*NN   * EE];          // 25856 x 256
__device__ float g_v  [BB*NN   * EE];
__device__ float g_att[TT      * EE];          // attention out_concat
__device__ float g_mh [2 * TT  * EE];          // two gate-slot contributions
__device__ int   g_topi[TT * 2];
__device__ float g_topg[TT * 2];
__device__ int   g_list[NE * TT];
__device__ int   g_count[NE];

// ============================================================
// Generic tiled SGEMM: C[M,256] = A[M,K] @ B[K,256]
// MODE 0: plain A.  MODE 1: A = concat(eln[M,256], attr[M,4]), K=260.
// BM=BN=64, BK=16, 256 threads, 4x4 per thread. M multiple of 64.
// ============================================================
template<int MODE>
__global__ void sgemm_kernel(const float* __restrict__ A,
                             const float* __restrict__ A2,
                             const float* __restrict__ Bm,
                             float* __restrict__ C,
                             int M, int K)
{
    __shared__ float As[16][64];
    __shared__ float Bs[16][64];
    const int m0 = blockIdx.x * 64;
    const int n0 = blockIdx.y * 64;
    const int tid = threadIdx.x;
    const int tx = tid & 15, ty = tid >> 4;

    float acc[4][4];
#pragma unroll
    for (int i = 0; i < 4; i++)
#pragma unroll
        for (int j = 0; j < 4; j++) acc[i][j] = 0.f;

    for (int k0 = 0; k0 < K; k0 += 16) {
#pragma unroll
        for (int it = 0; it < 4; it++) {
            int i = tid + it * 256;              // 64x16 = 1024 elems
            int m = i >> 4, kk = i & 15;
            int kg = k0 + kk;
            float val = 0.f;
            if (kg < K) {
                int row = m0 + m;
                if (MODE == 0) val = A[(size_t)row * K + kg];
                else           val = (kg < 256) ? A[(size_t)row * 256 + kg]
                                                : A2[(size_t)row * 4 + (kg - 256)];
            }
            As[kk][m] = val;
        }
#pragma unroll
        for (int it = 0; it < 4; it++) {
            int i = tid + it * 256;              // 16x64
            int kk = i >> 6, n = i & 63;
            int kg = k0 + kk;
            Bs[kk][n] = (kg < K) ? Bm[(size_t)kg * 256 + n0 + n] : 0.f;
        }
        __syncthreads();
#pragma unroll
        for (int kk = 0; kk < 16; kk++) {
            float4 a4 = *(const float4*)&As[kk][ty * 4];
            float4 b4 = *(const float4*)&Bs[kk][tx * 4];
            float av[4] = {a4.x, a4.y, a4.z, a4.w};
            float bv[4] = {b4.x, b4.y, b4.z, b4.w};
#pragma unroll
            for (int i = 0; i < 4; i++)
#pragma unroll
                for (int j = 0; j < 4; j++) acc[i][j] += av[i] * bv[j];
        }
        __syncthreads();
    }
#pragma unroll
    for (int i = 0; i < 4; i++) {
        int m = m0 + ty * 4 + i;
#pragma unroll
        for (int j = 0; j < 4; j++)
            C[(size_t)m * 256 + n0 + tx * 4 + j] = acc[i][j];
    }
}

// ============================================================
// Attention per (b, h): S = QK^T/4 + ninf, softmax, O = W V
// smem: sS[100*101] | sK[101*16] | sQV[101*16]
// ============================================================
__global__ void attn_kernel(const float* __restrict__ q,
                            const float* __restrict__ k,
                            const float* __restrict__ v,
                            const float* __restrict__ ninf,
                            float* __restrict__ outc)
{
    extern __shared__ float sm[];
    float* sS  = sm;                 // 10100
    float* sK  = sm + 10100;         // 1616
    float* sQV = sm + 10100 + 1616;  // 1616
    const int b = blockIdx.x, h = blockIdx.y;
    const int tid = threadIdx.x;

    const float* kb = k + ((size_t)b * NN) * EE + h * DD;
    const float* qb = q + ((size_t)b * PP) * EE + h * DD;
    const float* vb = v + ((size_t)b * NN) * EE + h * DD;

    for (int i = tid; i < NN * DD; i += 256) {
        int n = i >> 4, d = i & 15;
        sK[n * 16 + d] = kb[(size_t)n * EE + d];
    }
    for (int i = tid; i < PP * DD; i += 256) {
        int p = i >> 4, d = i & 15;
        sQV[p * 16 + d] = qb[(size_t)p * EE + d];
    }
    __syncthreads();

    const float* ninfb = ninf + (size_t)b * PP * NN;
    for (int i = tid; i < PP * NN; i += 256) {
        int p = i / NN, n = i - p * NN;
        const float4* q4 = (const float4*)&sQV[p * 16];
        const float4* k4 = (const float4*)&sK[n * 16];
        float s = 0.f;
#pragma unroll
        for (int d4 = 0; d4 < 4; d4++) {
            float4 a = q4[d4], c = k4[d4];
            s += a.x * c.x + a.y * c.y + a.z * c.z + a.w * c.w;
        }
        sS[i] = s * 0.25f + ninfb[i];
    }
    __syncthreads();

    // row softmax (warp per row)
    const int wid = tid >> 5, lane = tid & 31;
    for (int p = wid; p < PP; p += 8) {
        float* row = sS + p * NN;
        float mx = -1e30f;
        for (int n = lane; n < NN; n += 32) mx = fmaxf(mx, row[n]);
#pragma unroll
        for (int o = 16; o; o >>= 1) mx = fmaxf(mx, __shfl_xor_sync(~0u, mx, o));
        float sum = 0.f;
        for (int n = lane; n < NN; n += 32) { float e = __expf(row[n] - mx); row[n] = e; sum += e; }
#pragma unroll
        for (int o = 16; o; o >>= 1) sum += __shfl_xor_sync(~0u, sum, o);
        float inv = 1.f / sum;
        for (int n = lane; n < NN; n += 32) row[n] *= inv;
    }
    __syncthreads();

    // overwrite Q space with V
    for (int i = tid; i < NN * DD; i += 256) {
        int n = i >> 4, d = i & 15;
        sQV[n * 16 + d] = vb[(size_t)n * EE + d];
    }
    __syncthreads();

    float* ob = outc + ((size_t)b * PP) * EE + h * DD;
    for (int i = tid; i < PP * 4; i += 256) {
        int p = i >> 2, d0 = i & 3;
        float4 acc = {0.f, 0.f, 0.f, 0.f};
        const float* row = sS + p * NN;
        for (int n = 0; n < NN; n++) {
            float w = row[n];
            float4 vv = ((const float4*)&sQV[n * 16])[d0];
            acc.x += w * vv.x; acc.y += w * vv.y;
            acc.z += w * vv.z; acc.w += w * vv.w;
        }
        ((float4*)(ob + (size_t)p * EE))[d0] = acc;
    }
}

// ============================================================
// Routing: warp per token -> top2 of x@Wg + gate softmax
// ============================================================
__global__ void route_kernel(const float* __restrict__ x,
                             const float* __restrict__ Wg,
                             int* __restrict__ topi,
                             float* __restrict__ topg)
{
    const int wid = threadIdx.x >> 5, lane = threadIdx.x & 31;
    const int t = blockIdx.x * 8 + wid;
    if (t >= TT) return;
    float lg[8];
#pragma unroll
    for (int e = 0; e < 8; e++) lg[e] = 0.f;
    for (int f = lane; f < 256; f += 32) {
        float xv = x[(size_t)t * 256 + f];
        const float4* wg4 = (const float4*)&Wg[f * 8];
        float4 w0 = wg4[0], w1 = wg4[1];
        lg[0] += xv * w0.x; lg[1] += xv * w0.y; lg[2] += xv * w0.z; lg[3] += xv * w0.w;
        lg[4] += xv * w1.x; lg[5] += xv * w1.y; lg[6] += xv * w1.z; lg[7] += xv * w1.w;
    }
#pragma unroll
    for (int e = 0; e < 8; e++)
#pragma unroll
        for (int o = 16; o; o >>= 1) lg[e] += __shfl_xor_sync(~0u, lg[e], o);
    if (lane == 0) {
        float v1 = -1e30f, v2 = -1e30f; int i1 = 0, i2 = 0;
#pragma unroll
        for (int e = 0; e < 8; e++) {
            float vv = lg[e];
            if (vv > v1) { v2 = v1; i2 = i1; v1 = vv; i1 = e; }
            else if (vv > v2) { v2 = vv; i2 = e; }
        }
        float ex = expf(v2 - v1);
        float g1 = 1.f / (1.f + ex);
        topi[2 * t] = i1;  topi[2 * t + 1] = i2;
        topg[2 * t] = g1;  topg[2 * t + 1] = ex * g1;
    }
}

// ============================================================
// Deterministic per-expert token list (block scan, one block/expert)
// entry = token*2 + slot
// ============================================================
__global__ void build_lists_kernel(const int* __restrict__ topi,
                                   int* __restrict__ list,
                                   int* __restrict__ count)
{
    const int e = blockIdx.x;
    const int tid = threadIdx.x;
    __shared__ int scan[256];
    __shared__ int base_s;
    if (tid == 0) base_s = 0;
    __syncthreads();
    for (int c = 0; c < TT / 256; c++) {
        int t = c * 256 + tid;
        int slot = -1;
        if (topi[2 * t] == e) slot = 0;
        else if (topi[2 * t + 1] == e) slot = 1;
        int f = (slot >= 0) ? 1 : 0;
        scan[tid] = f;
        __syncthreads();
        for (int off = 1; off < 256; off <<= 1) {
            int vv = (tid >= off) ? scan[tid - off] : 0;
            __syncthreads();
            scan[tid] += vv;
            __syncthreads();
        }
        int tot = scan[255];
        int mybase = base_s;
        if (slot >= 0) list[e * TT + mybase + scan[tid] - 1] = t * 2 + slot;
        __syncthreads();
        if (tid == 0) base_s = mybase + tot;
        __syncthreads();
    }
    if (tid == 0) count[e] = base_s;
}

// ============================================================
// Gathered expert GEMM: for each list row, mh[slot][t] = g*(x@W_e + b_e)
// 64x64 tiles, grid (400, 4, 8)
// ============================================================
__global__ void expert_gemm_kernel(const float* __restrict__ x,
                                   const float* __restrict__ eW,
                                   const float* __restrict__ eb,
                                   const int* __restrict__ list,
                                   const int* __restrict__ count,
                                   const float* __restrict__ topg,
                                   float* __restrict__ mh)
{
    const int e = blockIdx.z;
    const int cnt = count[e];
    const int r0 = blockIdx.x * 64;
    if (r0 >= cnt) return;
    const int n0 = blockIdx.y * 64;

    __shared__ float As[16][64];
    __shared__ float Bs[16][64];
    __shared__ int   s_tok[64];
    __shared__ float s_gate[64];
    __shared__ int   s_slot[64];

    const int tid = threadIdx.x;
    if (tid < 64) {
        int r = r0 + tid;
        if (r < cnt) {
            int entry = list[e * TT + r];
            int t = entry >> 1, slot = entry & 1;
            s_tok[tid] = t; s_slot[tid] = slot;
            s_gate[tid] = topg[2 * t + slot];
        } else s_tok[tid] = -1;
    }
    __syncthreads();

    const int tx = tid & 15, ty = tid >> 4;
    float acc[4][4];
#pragma unroll
    for (int i = 0; i < 4; i++)
#pragma unroll
        for (int j = 0; j < 4; j++) acc[i][j] = 0.f;

    const float* We = eW + (size_t)e * 65536;
    for (int k0 = 0; k0 < 256; k0 += 16) {
#pragma unroll
        for (int it = 0; it < 4; it++) {
            int i = tid + it * 256;
            int m = i >> 4, kk = i & 15;
            int t = s_tok[m];
            As[kk][m] = (t >= 0) ? x[(size_t)t * 256 + k0 + kk] : 0.f;
        }
#pragma unroll
        for (int it = 0; it < 4; it++) {
            int i = tid + it * 256;
            int kk = i >> 6, n = i & 63;
            Bs[kk][n] = We[(size_t)(k0 + kk) * 256 + n0 + n];
        }
        __syncthreads();
#pragma unroll
        for (int kk = 0; kk < 16; kk++) {
            float4 a4 = *(const float4*)&As[kk][ty * 4];
            float4 b4 = *(const float4*)&Bs[kk][tx * 4];
            float av[4] = {a4.x, a4.y, a4.z, a4.w};
            float bv[4] = {b4.x, b4.y, b4.z, b4.w};
#pragma unroll
            for (int i = 0; i < 4; i++)
#pragma unroll
                for (int j = 0; j < 4; j++) acc[i][j] += av[i] * bv[j];
        }
        __syncthreads();
    }
#pragma unroll
    for (int i = 0; i < 4; i++) {
        int m = ty * 4 + i;
        int t = s_tok[m];
        if (t < 0) continue;
        float g = s_gate[m];
        int slot = s_slot[m];
        float* dst = mh + (size_t)slot * TT * 256 + (size_t)t * 256 + n0 + tx * 4;
        const float* bb = eb + e * 256 + n0 + tx * 4;
#pragma unroll
        for (int j = 0; j < 4; j++) dst[j] = g * (acc[i][j] + bb[j]);
    }
}

// ============================================================
// Final: score2 = (mh0+mh1) @ enc^T + bias + bias1, tanh clip,
//        softmax(score2 + ninf) -> out. One block per batch.
// smem: tiles sA[100*32] sB[101*32] then reused as sS[10100]
// ============================================================
__global__ void final_kernel(const float* __restrict__ mh,
                             const float* __restrict__ enc,
                             const float* __restrict__ bias,
                             const float* __restrict__ bias1,
                             const float* __restrict__ ninf,
                             float* __restrict__ out)
{
    extern __shared__ float sm[];
    float* sA = sm;            // 100*32
    float* sB = sm + 3200;     // 101*32
    float* sS = sm;            // 10100 (reuse after compute)
    const int b = blockIdx.x, tid = threadIdx.x;

    const float* mh0 = mh + (size_t)b * PP * 256;
    const float* mh1 = mh + (size_t)TT * 256 + (size_t)b * PP * 256;
    const float* encb = enc + (size_t)b * NN * 256;

    float acc[40];
#pragma unroll
    for (int j = 0; j < 40; j++) acc[j] = 0.f;

    for (int k0 = 0; k0 < 256; k0 += 32) {
        for (int i = tid; i < PP * 32; i += 256) {
            int p = i >> 5, kk = i & 31;
            sA[p * 32 + kk] = mh0[(size_t)p * 256 + k0 + kk] + mh1[(size_t)p * 256 + k0 + kk];
        }
        for (int i = tid; i < NN * 32; i += 256) {
            int n = i >> 5, kk = i & 31;
            sB[n * 32 + kk] = encb[(size_t)n * 256 + k0 + kk];
        }
        __syncthreads();
#pragma unroll 4
        for (int j = 0; j < 40; j++) {
            int idx = tid + j * 256;
            if (idx >= PP * NN) break;
            int p = idx / NN, n = idx - p * NN;
            const float4* a4 = (const float4*)&sA[p * 32];
            const float4* b4 = (const float4*)&sB[n * 32];
            float s = acc[j];
#pragma unroll
            for (int q = 0; q < 8; q++) {
                float4 a = a4[q], c = b4[q];
                s += a.x * c.x + a.y * c.y + a.z * c.z + a.w * c.w;
            }
            acc[j] = s;
        }
        __syncthreads();
    }

    const float* biasb  = bias  + (size_t)b * PP * NN;
    const float* bias1b = bias1 + (size_t)b * PP * NN;
    const float* ninfb  = ninf  + (size_t)b * PP * NN;
    for (int j = 0; j < 40; j++) {
        int idx = tid + j * 256;
        if (idx >= PP * NN) break;
        float s = acc[j] + biasb[idx] + bias1b[idx];
        s = 10.f * tanhf(s * 0.0625f);
        sS[idx] = s + ninfb[idx];
    }
    __syncthreads();

    const int wid = tid >> 5, lane = tid & 31;
    float* outb = out + (size_t)b * PP * NN;
    for (int p = wid; p < PP; p += 8) {
        float* row = sS + p * NN;
        float mx = -1e30f;
        for (int n = lane; n < NN; n += 32) mx = fmaxf(mx, row[n]);
#pragma unroll
        for (int o = 16; o; o >>= 1) mx = fmaxf(mx, __shfl_xor_sync(~0u, mx, o));
        float sum = 0.f;
        for (int n = lane; n < NN; n += 32) { float e = __expf(row[n] - mx); row[n] = e; sum += e; }
#pragma unroll
        for (int o = 16; o; o >>= 1) sum += __shfl_xor_sync(~0u, sum, o);
        float inv = 1.f / sum;
        for (int n = lane; n < NN; n += 32) outb[p * NN + n] = row[n] * inv;
    }
}

// ============================================================
// Host launcher
// ============================================================
extern "C" void kernel_launch(void* const* d_in, const int* in_sizes, int n_in,
                              void* d_out, int out_size)
{
    const float* eln   = (const float*)d_in[0];   // (B,P,E)
    const float* attr  = (const float*)d_in[1];   // (B,P,4)
    const float* enc   = (const float*)d_in[2];   // (B,N1,E)
    const float* ninf  = (const float*)d_in[3];   // (B,P,N1)
    const float* bias  = (const float*)d_in[4];   // (B,P,N1)
    const float* bias1 = (const float*)d_in[5];   // (B,P,N1)
    const float* Wq    = (const float*)d_in[6];   // (260,256)
    const float* Wk    = (const float*)d_in[7];   // (256,256)
    const float* Wv    = (const float*)d_in[8];   // (256,256)
    const float* Wg    = (const float*)d_in[9];   // (256,8)
    const float* eW    = (const float*)d_in[10];  // (8,256,256)
    const float* eb    = (const float*)d_in[11];  // (8,256)
    float* out = (float*)d_out;

    float *pq, *pk, *pv, *patt, *pmh, *ptopg;
    int *ptopi, *plist, *pcount;
    cudaGetSymbolAddress((void**)&pq,    g_q);
    cudaGetSymbolAddress((void**)&pk,    g_k);
    cudaGetSymbolAddress((void**)&pv,    g_v);
    cudaGetSymbolAddress((void**)&patt,  g_att);
    cudaGetSymbolAddress((void**)&pmh,   g_mh);
    cudaGetSymbolAddress((void**)&ptopi, g_topi);
    cudaGetSymbolAddress((void**)&ptopg, g_topg);
    cudaGetSymbolAddress((void**)&plist, g_list);
    cudaGetSymbolAddress((void**)&pcount,g_count);

    const int attn_smem  = (10100 + 1616 + 1616) * 4;   // 53328 B
    const int final_smem = 10100 * 4;                   // 40400 B
    cudaFuncSetAttribute(attn_kernel,  cudaFuncAttributeMaxDynamicSharedMemorySize, attn_smem);
    cudaFuncSetAttribute(final_kernel, cudaFuncAttributeMaxDynamicSharedMemorySize, final_smem);

    // 1-3: projections
    sgemm_kernel<1><<<dim3(TT / 64, 4), 256>>>(eln, attr, Wq, pq, TT, KQ);
    sgemm_kernel<0><<<dim3(BB * NN / 64, 4), 256>>>(enc, nullptr, Wk, pk, BB * NN, 256);
    sgemm_kernel<0><<<dim3(BB * NN / 64, 4), 256>>>(enc, nullptr, Wv, pv, BB * NN, 256);
    // 4: attention
    attn_kernel<<<dim3(BB, HH), 256, attn_smem>>>(pq, pk, pv, ninf, patt);
    // 5: routing
    route_kernel<<<TT / 8, 256>>>(patt, Wg, ptopi, ptopg);
    // 6: expert lists (deterministic)
    build_lists_kernel<<<NE, 256>>>(ptopi, plist, pcount);
    // 7: gathered expert GEMM into two slot buffers
    expert_gemm_kernel<<<dim3(TT / 64, 4, NE), 256>>>(patt, eW, eb, plist, pcount, ptopg, pmh);
    // 8: pointer scores + softmax
    final_kernel<<<BB, 256, final_smem>>>(pmh, enc, bias, bias1, ninf, out);
}

// round 2
// speedup vs baseline: 2.2984x; 2.2984x over previous
#include <cuda_runtime.h>
#include <cuda_bf16.h>
#include <cstdint>
#include <cstddef>

// ---------------- problem constants ----------------
#define BB   256
#define PP   100
#define NN   101
#define EE   256
#define HH   16
#define NE   8
#define TT   (BB*PP)

// ---------------- scratch ----------------
__device__ float g_q  [TT    * EE];
__device__ float g_k  [BB*NN * EE];
__device__ float g_v  [BB*NN * EE];
__device__ float g_att[TT    * EE];
__device__ float g_mh [2*TT  * EE];
__device__ float g_s2 [BB*PP * NN];
__device__ int   g_topi[TT * 2];
__device__ float g_topg[TT * 2];
__device__ int   g_list[NE * TT];
__device__ int   g_count[NE];

// ---------------- tf32 helpers ----------------
__device__ __forceinline__ uint32_t f2tf32(float x) {
    uint32_t u; asm("cvt.rna.tf32.f32 %0, %1;" : "=r"(u) : "f"(x)); return u;
}
__device__ __forceinline__ void split2(float x, float& hi, float& lo) {
    uint32_t h = f2tf32(x);
    float hf = __uint_as_float(h);
    hi = hf;
    lo = __uint_as_float(f2tf32(x - hf));
}
__device__ __forceinline__ void mma8(float c[4],
    uint32_t a0, uint32_t a1, uint32_t a2, uint32_t a3,
    uint32_t b0, uint32_t b1)
{
    asm volatile(
        "mma.sync.aligned.m16n8k8.row.col.f32.tf32.tf32.f32 "
        "{%0,%1,%2,%3}, {%4,%5,%6,%7}, {%8,%9}, {%0,%1,%2,%3};"
        : "+f"(c[0]), "+f"(c[1]), "+f"(c[2]), "+f"(c[3])
        : "r"(a0), "r"(a1), "r"(a2), "r"(a3), "r"(b0), "r"(b1));
}

// ============================================================
// tf32x2 GEMM, 128x128 tile, BK=16, 512 threads (16 warps 2x8),
// warp tile 64x16 (mt=4, nt=2). 3 mma per tile pair (error-comp).
// MODE 0: C[M,256] = A[M,K] @ B[K,256]                 (k/v proj)
// MODE 1: A = concat(A[M,256], A2[M,4]), K=260          (q proj)
// MODE 2: gathered expert GEMM + gate/bias epilogue
// MODE 3: per-batch C[100,101] = (mh0+mh1)[100,256] @ enc^T[256,101]
//         fused epilogue: +bias+bias1, 10*tanh(/16), +ninf -> g_s2
// ============================================================
#define LDA 20
#define LDB 136

template<int MODE>
__launch_bounds__(512)
__global__ void gemm_tf32(const float* __restrict__ A,
                          const float* __restrict__ A2,
                          const float* __restrict__ Bm,
                          float* __restrict__ Cout,
                          int M, int K,
                          const int*   __restrict__ list,
                          const int*   __restrict__ count,
                          const float* __restrict__ topg,
                          const float* __restrict__ eb,
                          const float* __restrict__ bias,
                          const float* __restrict__ bias1,
                          const float* __restrict__ ninf)
{
    __shared__ float Ah[128 * LDA], Al[128 * LDA];
    __shared__ float Bh[16 * LDB],  Bl[16 * LDB];
    __shared__ int   s_tok[128];
    __shared__ float s_gate[128];
    __shared__ int   s_slot[128];

    const int tid = threadIdx.x;
    const int m0 = blockIdx.x * 128;
    const int n0 = blockIdx.y * 128;
    const int bz = blockIdx.z;
    int e = 0, cnt = 0;

    const float* Aro = A;
    const float* Bro = Bm;

    if (MODE == 2) {
        e = bz;
        cnt = count[e];
        if (m0 >= cnt) return;
        Bro = Bm + (size_t)e * 65536;
        if (tid < 128) {
            int r = m0 + tid;
            if (r < cnt) {
                int entry = list[e * TT + r];
                s_tok[tid]  = entry >> 1;
                s_slot[tid] = entry & 1;
                s_gate[tid] = topg[entry];
            } else s_tok[tid] = -1;
        }
        __syncthreads();
    }
    if (MODE == 3) {
        Aro = A  + (size_t)bz * PP * EE;
        Bro = Bm + (size_t)bz * NN * EE;
    }

    const int wid = tid >> 5, lane = tid & 31;
    const int wm = wid & 1;          // 0..1 (64-row halves)
    const int wn = wid >> 1;         // 0..7 (16-col slices)
    const int g  = lane >> 2;        // 0..7
    const int tg = lane & 3;         // 0..3

    float c[4][2][4];
#pragma unroll
    for (int mt = 0; mt < 4; mt++)
#pragma unroll
        for (int nt = 0; nt < 2; nt++)
#pragma unroll
            for (int j = 0; j < 4; j++) c[mt][nt][j] = 0.f;

    for (int k0 = 0; k0 < K; k0 += 16) {
        // ---- load + split A tile (128x16) ----
#pragma unroll
        for (int it = 0; it < 4; it++) {
            int idx = it * 512 + tid;
            int m = idx >> 4, kk = idx & 15;
            int kg = k0 + kk;
            float v = 0.f;
            if (MODE == 0) {
                if (kg < K) v = Aro[(size_t)(m0 + m) * K + kg];
            } else if (MODE == 1) {
                if (kg < 256)     v = Aro[(size_t)(m0 + m) * 256 + kg];
                else if (kg < K)  v = A2[(size_t)(m0 + m) * 4 + (kg - 256)];
            } else if (MODE == 2) {
                int t = s_tok[m];
                if (t >= 0 && kg < K) v = Aro[(size_t)t * 256 + kg];
            } else {
                if (m < PP && kg < K)
                    v = Aro[(size_t)m * 256 + kg]
                      + Aro[(size_t)TT * EE + (size_t)m * 256 + kg];
            }
            float hi, lo; split2(v, hi, lo);
            Ah[m * LDA + kk] = hi;
            Al[m * LDA + kk] = lo;
        }
        // ---- load + split B tile (16x128) ----
#pragma unroll
        for (int it = 0; it < 4; it++) {
            int idx = it * 512 + tid;
            float v = 0.f;
            int kk, n;
            if (MODE == 3) {
                n = idx >> 4; kk = idx & 15;
                int kg = k0 + kk;
                if (n < NN && kg < K) v = Bro[(size_t)n * 256 + kg];
            } else {
                kk = idx >> 7; n = idx & 127;
                int kg = k0 + kk;
                if (kg < K) v = Bro[(size_t)kg * 256 + n0 + n];
            }
            float hi, lo; split2(v, hi, lo);
            Bh[kk * LDB + n] = hi;
            Bl[kk * LDB + n] = lo;
        }
        __syncthreads();

#pragma unroll
        for (int ks = 0; ks < 16; ks += 8) {
            uint32_t ah[4][4], al[4][4], bh[2][2], bl[2][2];
#pragma unroll
            for (int mt = 0; mt < 4; mt++) {
                int r = wm * 64 + mt * 16;
                ah[mt][0] = __float_as_uint(Ah[(r + g)     * LDA + ks + tg]);
                ah[mt][1] = __float_as_uint(Ah[(r + g + 8) * LDA + ks + tg]);
                ah[mt][2] = __float_as_uint(Ah[(r + g)     * LDA + ks + tg + 4]);
                ah[mt][3] = __float_as_uint(Ah[(r + g + 8) * LDA + ks + tg + 4]);
                al[mt][0] = __float_as_uint(Al[(r + g)     * LDA + ks + tg]);
                al[mt][1] = __float_as_uint(Al[(r + g + 8) * LDA + ks + tg]);
                al[mt][2] = __float_as_uint(Al[(r + g)     * LDA + ks + tg + 4]);
                al[mt][3] = __float_as_uint(Al[(r + g + 8) * LDA + ks + tg + 4]);
            }
#pragma unroll
            for (int nt = 0; nt < 2; nt++) {
                int cc = wn * 16 + nt * 8 + g;
                bh[nt][0] = __float_as_uint(Bh[(ks + tg)     * LDB + cc]);
                bh[nt][1] = __float_as_uint(Bh[(ks + tg + 4) * LDB + cc]);
                bl[nt][0] = __float_as_uint(Bl[(ks + tg)     * LDB + cc]);
                bl[nt][1] = __float_as_uint(Bl[(ks + tg + 4) * LDB + cc]);
            }
#pragma unroll
            for (int mt = 0; mt < 4; mt++)
#pragma unroll
                for (int nt = 0; nt < 2; nt++) {
                    mma8(c[mt][nt], ah[mt][0], ah[mt][1], ah[mt][2], ah[mt][3],
                         bh[nt][0], bh[nt][1]);
                    mma8(c[mt][nt], al[mt][0], al[mt][1], al[mt][2], al[mt][3],
                         bh[nt][0], bh[nt][1]);
                    mma8(c[mt][nt], ah[mt][0], ah[mt][1], ah[mt][2], ah[mt][3],
                         bl[nt][0], bl[nt][1]);
                }
        }
        __syncthreads();
    }

    // ---- epilogue ----
#pragma unroll
    for (int mt = 0; mt < 4; mt++) {
#pragma unroll
        for (int nt = 0; nt < 2; nt++) {
            int ml = wm * 64 + mt * 16 + g;
            int nl = wn * 16 + nt * 8 + tg * 2;
#pragma unroll
            for (int half = 0; half < 2; half++) {
                int row = ml + half * 8;
#pragma unroll
                for (int j = 0; j < 2; j++) {
                    float val = c[mt][nt][half * 2 + j];
                    int col = nl + j;
                    if (MODE <= 1) {
                        Cout[(size_t)(m0 + row) * 256 + n0 + col] = val;
                    } else if (MODE == 2) {
                        int t = s_tok[row];
                        if (t >= 0) {
                            float o = s_gate[row] * (val + eb[e * 256 + n0 + col]);
                            Cout[(size_t)s_slot[row] * TT * EE +
                                 (size_t)t * 256 + n0 + col] = o;
                        }
                    } else {
                        if (row < PP && col < NN) {
                            size_t off = (size_t)bz * PP * NN + (size_t)row * NN + col;
                            float s = val + bias[off] + bias1[off];
                            s = 10.f * tanhf(s * 0.0625f);
                            Cout[off] = s + ninf[off];
                        }
                    }
                }
            }
        }
    }
}

// ============================================================
// Attention: block (b,h), 128 threads, thread-per-query-row.
// smem: sS[100*101] (ninf preloaded, then scores/weights),
//       sK[101*16], sV[101*16].
// ============================================================
__global__ __launch_bounds__(128)
void attn_kernel(const float* __restrict__ q,
                 const float* __restrict__ k,
                 const float* __restrict__ v,
                 const float* __restrict__ ninf,
                 float* __restrict__ outc)
{
    extern __shared__ float sm[];
    float* sS = sm;                  // 10100
    float* sK = sm + 10100;          // 1616
    float* sV = sm + 10100 + 1616;   // 1616
    const int b = blockIdx.x, h = blockIdx.y;
    const int tid = threadIdx.x;

    const float4* nf4 = (const float4*)(ninf + (size_t)b * PP * NN);
    float4* sS4 = (float4*)sS;
    for (int i = tid; i < PP * NN / 4; i += 128) sS4[i] = nf4[i];

    const float* kb = k + (size_t)b * NN * EE + h * 16;
    const float* vb = v + (size_t)b * NN * EE + h * 16;
    for (int i = tid; i < NN * 4; i += 128) {
        int n = i >> 2, c = i & 3;
        *(float4*)(sK + n * 16 + c * 4) = *(const float4*)(kb + (size_t)n * EE + c * 4);
        *(float4*)(sV + n * 16 + c * 4) = *(const float4*)(vb + (size_t)n * EE + c * 4);
    }
    __syncthreads();

    if (tid < PP) {
        const int p = tid;
        const float* qb = q + ((size_t)b * PP + p) * EE + h * 16;
        float4 q0 = *(const float4*)(qb);
        float4 q1 = *(const float4*)(qb + 4);
        float4 q2 = *(const float4*)(qb + 8);
        float4 q3 = *(const float4*)(qb + 12);
        float* row = sS + p * NN;

        float mx = -1e30f;
        for (int n = 0; n < NN; n++) {
            const float4* kk4 = (const float4*)(sK + n * 16);
            float4 k0 = kk4[0], k1 = kk4[1], k2 = kk4[2], k3 = kk4[3];
            float s0 = q0.x * k0.x + q0.y * k0.y + q0.z * k0.z + q0.w * k0.w;
            float s1 = q1.x * k1.x + q1.y * k1.y + q1.z * k1.z + q1.w * k1.w;
            float s2 = q2.x * k2.x + q2.y * k2.y + q2.z * k2.z + q2.w * k2.w;
            float s3 = q3.x * k3.x + q3.y * k3.y + q3.z * k3.z + q3.w * k3.w;
            float sc = (s0 + s1 + s2 + s3) * 0.25f + row[n];
            row[n] = sc;
            mx = fmaxf(mx, sc);
        }
        float sum = 0.f;
        for (int n = 0; n < NN; n++) {
            float e = __expf(row[n] - mx);
            row[n] = e;
            sum += e;
        }
        float inv = 1.f / sum;

        float4 o0 = {0,0,0,0}, o1 = {0,0,0,0}, o2 = {0,0,0,0}, o3 = {0,0,0,0};
        for (int n = 0; n < NN; n++) {
            float w = row[n];
            const float4* vv4 = (const float4*)(sV + n * 16);
            float4 v0 = vv4[0], v1 = vv4[1], v2 = vv4[2], v3 = vv4[3];
            o0.x += w * v0.x; o0.y += w * v0.y; o0.z += w * v0.z; o0.w += w * v0.w;
            o1.x += w * v1.x; o1.y += w * v1.y; o1.z += w * v1.z; o1.w += w * v1.w;
            o2.x += w * v2.x; o2.y += w * v2.y; o2.z += w * v2.z; o2.w += w * v2.w;
            o3.x += w * v3.x; o3.y += w * v3.y; o3.z += w * v3.z; o3.w += w * v3.w;
        }
        float* ob = outc + ((size_t)b * PP + p) * EE + h * 16;
        o0.x *= inv; o0.y *= inv; o0.z *= inv; o0.w *= inv;
        o1.x *= inv; o1.y *= inv; o1.z *= inv; o1.w *= inv;
        o2.x *= inv; o2.y *= inv; o2.z *= inv; o2.w *= inv;
        o3.x *= inv; o3.y *= inv; o3.z *= inv; o3.w *= inv;
        ((float4*)ob)[0] = o0; ((float4*)ob)[1] = o1;
        ((float4*)ob)[2] = o2; ((float4*)ob)[3] = o3;
    }
}

// ============================================================
// Routing: warp per token -> top2 of x@Wg + gate softmax
// ============================================================
__global__ void route_kernel(const float* __restrict__ x,
                             const float* __restrict__ Wg,
                             int* __restrict__ topi,
                             float* __restrict__ topg)
{
    const int wid = threadIdx.x >> 5, lane = threadIdx.x & 31;
    const int t = blockIdx.x * 8 + wid;
    if (t >= TT) return;
    float lg[8];
#pragma unroll
    for (int e = 0; e < 8; e++) lg[e] = 0.f;
    for (int f = lane; f < 256; f += 32) {
        float xv = x[(size_t)t * 256 + f];
        const float4* wg4 = (const float4*)&Wg[f * 8];
        float4 w0 = wg4[0], w1 = wg4[1];
        lg[0] += xv * w0.x; lg[1] += xv * w0.y; lg[2] += xv * w0.z; lg[3] += xv * w0.w;
        lg[4] += xv * w1.x; lg[5] += xv * w1.y; lg[6] += xv * w1.z; lg[7] += xv * w1.w;
    }
#pragma unroll
    for (int e = 0; e < 8; e++)
#pragma unroll
        for (int o = 16; o; o >>= 1) lg[e] += __shfl_xor_sync(~0u, lg[e], o);
    if (lane == 0) {
        float v1 = -1e30f, v2 = -1e30f; int i1 = 0, i2 = 0;
#pragma unroll
        for (int e = 0; e < 8; e++) {
            float vv = lg[e];
            if (vv > v1) { v2 = v1; i2 = i1; v1 = vv; i1 = e; }
            else if (vv > v2) { v2 = vv; i2 = e; }
        }
        float ex = expf(v2 - v1);
        float g1 = 1.f / (1.f + ex);
        topi[2 * t] = i1;  topi[2 * t + 1] = i2;
        topg[2 * t] = g1;  topg[2 * t + 1] = ex * g1;
    }
}

// ============================================================
// Per-expert token list via ballot scan (deterministic)
// ============================================================
__global__ void build_lists_kernel(const int* __restrict__ topi,
                                   int* __restrict__ list,
                                   int* __restrict__ count)
{
    const int e = blockIdx.x;
    const int tid = threadIdx.x;
    const int wid = tid >> 5, lane = tid & 31;
    __shared__ int wtot[8];
    __shared__ int base;
    if (tid == 0) base = 0;
    __syncthreads();
    for (int c = 0; c < TT / 256; c++) {
        int t = c * 256 + tid;
        int slot = -1;
        int a = topi[2 * t], bq = topi[2 * t + 1];
        if (a == e) slot = 0; else if (bq == e) slot = 1;
        unsigned mask = __ballot_sync(0xffffffffu, slot >= 0);
        int wpre = __popc(mask & ((1u << lane) - 1));
        if (lane == 0) wtot[wid] = __popc(mask);
        __syncthreads();
        int wbase = 0, ctot = 0;
#pragma unroll
        for (int w = 0; w < 8; w++) {
            if (w < wid) wbase += wtot[w];
            ctot += wtot[w];
        }
        if (slot >= 0) list[e * TT + base + wbase + wpre] = t * 2 + slot;
        __syncthreads();
        if (tid == 0) base += ctot;
        __syncthreads();
    }
    if (tid == 0) count[e] = base;
}

// ============================================================
// Output softmax: warp per row over g_s2 (already has ninf added)
// ============================================================
__global__ void softmax_out_kernel(const float* __restrict__ s2,
                                   float* __restrict__ out)
{
    const int wid = threadIdx.x >> 5, lane = threadIdx.x & 31;
    const int r = blockIdx.x * 8 + wid;
    if (r >= TT) return;
    const float* row = s2 + (size_t)r * NN;
    float vals[4];
    float mx = -1e30f;
#pragma unroll
    for (int i = 0; i < 4; i++) {
        int n = lane + i * 32;
        vals[i] = (n < NN) ? row[n] : -1e30f;
        mx = fmaxf(mx, vals[i]);
    }
#pragma unroll
    for (int o = 16; o; o >>= 1) mx = fmaxf(mx, __shfl_xor_sync(~0u, mx, o));
    float sum = 0.f;
#pragma unroll
    for (int i = 0; i < 4; i++) {
        vals[i] = __expf(vals[i] - mx);
        sum += vals[i];
    }
#pragma unroll
    for (int o = 16; o; o >>= 1) sum += __shfl_xor_sync(~0u, sum, o);
    float inv = 1.f / sum;
    float* orow = out + (size_t)r * NN;
#pragma unroll
    for (int i = 0; i < 4; i++) {
        int n = lane + i * 32;
        if (n < NN) orow[n] = vals[i] * inv;
    }
}

// ============================================================
// Host launcher
// ============================================================
extern "C" void kernel_launch(void* const* d_in, const int* in_sizes, int n_in,
                              void* d_out, int out_size)
{
    const float* eln   = (const float*)d_in[0];
    const float* attr  = (const float*)d_in[1];
    const float* enc   = (const float*)d_in[2];
    const float* ninf  = (const float*)d_in[3];
    const float* bias  = (const float*)d_in[4];
    const float* bias1 = (const float*)d_in[5];
    const float* Wq    = (const float*)d_in[6];
    const float* Wk    = (const float*)d_in[7];
    const float* Wv    = (const float*)d_in[8];
    const float* Wg    = (const float*)d_in[9];
    const float* eW    = (const float*)d_in[10];
    const float* eb    = (const float*)d_in[11];
    float* out = (float*)d_out;

    float *pq, *pk, *pv, *patt, *pmh, *ptopg, *ps2;
    int *ptopi, *plist, *pcount;
    cudaGetSymbolAddress((void**)&pq,    g_q);
    cudaGetSymbolAddress((void**)&pk,    g_k);
    cudaGetSymbolAddress((void**)&pv,    g_v);
    cudaGetSymbolAddress((void**)&patt,  g_att);
    cudaGetSymbolAddress((void**)&pmh,   g_mh);
    cudaGetSymbolAddress((void**)&ps2,   g_s2);
    cudaGetSymbolAddress((void**)&ptopi, g_topi);
    cudaGetSymbolAddress((void**)&ptopg, g_topg);
    cudaGetSymbolAddress((void**)&plist, g_list);
    cudaGetSymbolAddress((void**)&pcount,g_count);

    const int attn_smem = (PP * NN + 2 * NN * 16) * 4;   // 53328 B
    cudaFuncSetAttribute(attn_kernel,
        cudaFuncAttributeMaxDynamicSharedMemorySize, attn_smem);

    // q/k/v projections (tf32x2)
    gemm_tf32<1><<<dim3(TT / 128, 2, 1), 512>>>(eln, attr, Wq, pq, TT, 260,
        nullptr, nullptr, nullptr, nullptr, nullptr, nullptr, nullptr);
    gemm_tf32<0><<<dim3(BB * NN / 128, 2, 1), 512>>>(enc, nullptr, Wk, pk, BB * NN, 256,
        nullptr, nullptr, nullptr, nullptr, nullptr, nullptr, nullptr);
    gemm_tf32<0><<<dim3(BB * NN / 128, 2, 1), 512>>>(enc, nullptr, Wv, pv, BB * NN, 256,
        nullptr, nullptr, nullptr, nullptr, nullptr, nullptr, nullptr);
    // attention
    attn_kernel<<<dim3(BB, HH), 128, attn_smem>>>(pq, pk, pv, ninf, patt);
    // routing + lists
    route_kernel<<<TT / 8, 256>>>(patt, Wg, ptopi, ptopg);
    build_lists_kernel<<<NE, 256>>>(ptopi, plist, pcount);
    // gathered expert GEMM (tf32x2), gate+bias fused
    gemm_tf32<2><<<dim3(TT / 128, 2, NE), 512>>>(patt, nullptr, eW, pmh, TT, 256,
        plist, pcount, ptopg, eb, nullptr, nullptr, nullptr);
    // pointer-score GEMM (tf32x2) with fused bias/tanh/ninf epilogue
    gemm_tf32<3><<<dim3(1, 1, BB), 512>>>(pmh, nullptr, enc, ps2, PP, 256,
        nullptr, nullptr, nullptr, nullptr, bias, bias1, ninf);
    // output softmax
    softmax_out_kernel<<<(TT + 7) / 8, 256>>>(ps2, out);
}

// round 3
// speedup vs baseline: 2.5188x; 1.0959x over previous
#include <cuda_runtime.h>
#include <cuda_bf16.h>
#include <cstdint>
#include <cstddef>

// ---------------- problem constants ----------------
#define BB   256
#define PP   100
#define NN   101
#define EE   256
#define HH   16
#define NE   8
#define TT   (BB*PP)

// ---------------- scratch ----------------
__device__ float g_q  [TT    * EE];
__device__ float g_k  [BB*NN * EE];
__device__ float g_v  [BB*NN * EE];
__device__ float g_att[TT    * EE];
__device__ float g_mh [2*TT  * EE];
__device__ float g_s2 [BB*PP * NN];
__device__ int   g_topi[TT * 2];
__device__ float g_topg[TT * 2];
__device__ int   g_list[NE * TT];
__device__ int   g_count[NE];

// ---------------- tf32 helpers ----------------
__device__ __forceinline__ uint32_t f2tf32(float x) {
    uint32_t u; asm("cvt.rna.tf32.f32 %0, %1;" : "=r"(u) : "f"(x)); return u;
}
__device__ __forceinline__ float2 split2(float x) {
    float hi = __uint_as_float(f2tf32(x));
    float lo = __uint_as_float(f2tf32(x - hi));
    return make_float2(hi, lo);
}
__device__ __forceinline__ void mma8(float c[4],
    float a0, float a1, float a2, float a3, float b0, float b1)
{
    asm volatile(
        "mma.sync.aligned.m16n8k8.row.col.f32.tf32.tf32.f32 "
        "{%0,%1,%2,%3}, {%4,%5,%6,%7}, {%8,%9}, {%0,%1,%2,%3};"
        : "+f"(c[0]), "+f"(c[1]), "+f"(c[2]), "+f"(c[3])
        : "r"(__float_as_uint(a0)), "r"(__float_as_uint(a1)),
          "r"(__float_as_uint(a2)), "r"(__float_as_uint(a3)),
          "r"(__float_as_uint(b0)), "r"(__float_as_uint(b1)));
}

// ============================================================
// tf32x3 GEMM, 128x128 block tile, BK=16, 256 threads (8 warps
// 2x4), warp tile 64x32 (mt=4, nt=4). hi/lo interleaved float2
// smem, 2-stage double buffer, register prefetch.
// MODE 0: C[M,256] = A[M,K=256] @ B[256,256]           (k/v proj)
// MODE 1: A = concat(A[M,256], A2[M,4]), K=260          (q proj)
// MODE 2: gathered expert GEMM + gate/bias epilogue
// MODE 3: per-batch C[100,101] = (mh0+mh1)[100,256] @ enc^T
//         fused: +bias+bias1, 10*tanh(/16), +ninf -> g_s2
// ============================================================
#define PA 20    // float2 pitch per A row (16 + 4 pad)
#define PB 132   // float2 pitch per B row (128 + 4 pad)
#define GEMM_SMEM ((2*128*PA + 2*16*PB) * 8 + 128*12)

template<int MODE>
__launch_bounds__(256)
__global__ void gemm_tf32(const float* __restrict__ A,
                          const float* __restrict__ A2,
                          const float* __restrict__ Bm,
                          float* __restrict__ Cout,
                          int M, int K,
                          const int*   __restrict__ list,
                          const int*   __restrict__ count,
                          const float* __restrict__ topg,
                          const float* __restrict__ eb,
                          const float* __restrict__ bias,
                          const float* __restrict__ bias1,
                          const float* __restrict__ ninf)
{
    extern __shared__ float2 smem2[];
    float2* As = smem2;                          // 2 stages x 128*PA
    float2* Bs = smem2 + 2 * 128 * PA;           // 2 stages x 16*PB
    int*    s_tok  = (int*)  (smem2 + 2*128*PA + 2*16*PB);
    float*  s_gate = (float*)(s_tok + 128);
    int*    s_slot = (int*)  (s_gate + 128);

    const int tid = threadIdx.x;
    const int m0 = blockIdx.x * 128;
    const int n0 = blockIdx.y * 128;
    const int bz = blockIdx.z;
    int e = 0, cnt = 0;

    const float* Aro = A;
    const float* Bro = Bm;

    if (MODE == 2) {
        e = bz;
        cnt = count[e];
        if (m0 >= cnt) return;
        Bro = Bm + (size_t)e * 65536;
        if (tid < 128) {
            int r = m0 + tid;
            if (r < cnt) {
                int entry = list[e * TT + r];
                s_tok[tid]  = entry >> 1;
                s_slot[tid] = entry & 1;
                s_gate[tid] = topg[entry];
            } else s_tok[tid] = -1;
        }
        __syncthreads();
    }
    if (MODE == 3) {
        Aro = A  + (size_t)bz * PP * EE;
        Bro = Bm + (size_t)bz * NN * EE;
    }

    const int NT = (MODE == 1) ? 17 : 16;

    const int wid = tid >> 5, lane = tid & 31;
    const int wm = wid & 1;          // 0..1
    const int wn = wid >> 1;         // 0..3
    const int g  = lane >> 2;        // 0..7
    const int tg = lane & 3;         // 0..3

    // A-load indexing: idx4 over 512 float4s of a 128x16 tile
    const int amA[2] = { (0*256 + tid) >> 2, (1*256 + tid) >> 2 };
    const int akA    = (tid & 3) * 4;     // same c4 for both its
    // B-load indexing (MODE != 3): kk row + 4-float col group
    const int bkk[2] = { (0*256 + tid) >> 5, (1*256 + tid) >> 5 };
    const int bnn    = (tid & 31) * 4;
    // B-load indexing (MODE == 3): column-major gather
    const int b3n[2] = { (0*256 + tid) >> 2, (1*256 + tid) >> 2 };

    float4 av[2], bv[2];

    // ---------- prefetch helpers (inlined by templates) ----------
    auto loadA = [&](int k0) {
#pragma unroll
        for (int it = 0; it < 2; it++) {
            int m = amA[it];
            int kg = k0 + akA;
            float4 v = make_float4(0.f, 0.f, 0.f, 0.f);
            if (MODE == 1 && k0 == 256) {
                if (akA == 0) v = *(const float4*)(A2 + (size_t)(m0 + m) * 4);
            } else if (MODE == 2) {
                int t = s_tok[m];
                if (t >= 0) v = *(const float4*)(Aro + (size_t)t * 256 + kg);
            } else if (MODE == 3) {
                if (m < PP) {
                    float4 x = *(const float4*)(Aro + (size_t)m * 256 + kg);
                    float4 y = *(const float4*)(Aro + (size_t)TT * EE + (size_t)m * 256 + kg);
                    v = make_float4(x.x + y.x, x.y + y.y, x.z + y.z, x.w + y.w);
                }
            } else {
                v = *(const float4*)(Aro + (size_t)(m0 + m) * 256 + kg);
            }
            av[it] = v;
        }
    };
    auto loadB = [&](int k0) {
#pragma unroll
        for (int it = 0; it < 2; it++) {
            float4 v = make_float4(0.f, 0.f, 0.f, 0.f);
            if (MODE == 3) {
                int n = b3n[it];
                if (n < NN) v = *(const float4*)(Bro + (size_t)n * 256 + k0 + akA);
            } else {
                int kg = k0 + bkk[it];
                if (kg < K) v = *(const float4*)(Bro + (size_t)kg * 256 + n0 + bnn);
            }
            bv[it] = v;
        }
    };
    auto storeTile = [&](int stg) {
        float2* Ad = As + stg * 128 * PA;
        float2* Bd = Bs + stg * 16 * PB;
#pragma unroll
        for (int it = 0; it < 2; it++) {
            float2 s0 = split2(av[it].x), s1 = split2(av[it].y);
            float2 s2 = split2(av[it].z), s3 = split2(av[it].w);
            float4* dst = (float4*)(Ad + amA[it] * PA + akA);
            dst[0] = make_float4(s0.x, s0.y, s1.x, s1.y);
            dst[1] = make_float4(s2.x, s2.y, s3.x, s3.y);
        }
#pragma unroll
        for (int it = 0; it < 2; it++) {
            float2 s0 = split2(bv[it].x), s1 = split2(bv[it].y);
            float2 s2 = split2(bv[it].z), s3 = split2(bv[it].w);
            if (MODE == 3) {
                int n = b3n[it];
                Bd[(akA + 0) * PB + n] = s0;
                Bd[(akA + 1) * PB + n] = s1;
                Bd[(akA + 2) * PB + n] = s2;
                Bd[(akA + 3) * PB + n] = s3;
            } else {
                float4* dst = (float4*)(Bd + bkk[it] * PB + bnn);
                dst[0] = make_float4(s0.x, s0.y, s1.x, s1.y);
                dst[1] = make_float4(s2.x, s2.y, s3.x, s3.y);
            }
        }
    };

    float c[4][4][4];
#pragma unroll
    for (int mt = 0; mt < 4; mt++)
#pragma unroll
        for (int nt = 0; nt < 4; nt++)
#pragma unroll
            for (int j = 0; j < 4; j++) c[mt][nt][j] = 0.f;

    // ---------- prologue ----------
    loadA(0); loadB(0);
    storeTile(0);
    __syncthreads();

    int cur = 0;
    for (int t = 0; t < NT; t++) {
        if (t + 1 < NT) { loadA((t + 1) * 16); loadB((t + 1) * 16); }

        const float2* Ac = As + cur * 128 * PA;
        const float2* Bc = Bs + cur * 16 * PB;
#pragma unroll
        for (int ks = 0; ks < 16; ks += 8) {
            float2 a2[4][4];
            float2 b2[4][2];
#pragma unroll
            for (int mt = 0; mt < 4; mt++) {
                int rb = wm * 64 + mt * 16;
                a2[mt][0] = Ac[(rb + g)     * PA + ks + tg];
                a2[mt][1] = Ac[(rb + g + 8) * PA + ks + tg];
                a2[mt][2] = Ac[(rb + g)     * PA + ks + tg + 4];
                a2[mt][3] = Ac[(rb + g + 8) * PA + ks + tg + 4];
            }
#pragma unroll
            for (int nt = 0; nt < 4; nt++) {
                int cc = wn * 32 + nt * 8 + g;
                b2[nt][0] = Bc[(ks + tg)     * PB + cc];
                b2[nt][1] = Bc[(ks + tg + 4) * PB + cc];
            }
#pragma unroll
            for (int mt = 0; mt < 4; mt++)
#pragma unroll
                for (int nt = 0; nt < 4; nt++) {
                    mma8(c[mt][nt], a2[mt][0].x, a2[mt][1].x, a2[mt][2].x, a2[mt][3].x,
                         b2[nt][0].x, b2[nt][1].x);
                    mma8(c[mt][nt], a2[mt][0].y, a2[mt][1].y, a2[mt][2].y, a2[mt][3].y,
                         b2[nt][0].x, b2[nt][1].x);
                    mma8(c[mt][nt], a2[mt][0].x, a2[mt][1].x, a2[mt][2].x, a2[mt][3].x,
                         b2[nt][0].y, b2[nt][1].y);
                }
        }
        if (t + 1 < NT) {
            storeTile(cur ^ 1);
            __syncthreads();
            cur ^= 1;
        }
    }

    // ---------- epilogue ----------
#pragma unroll
    for (int mt = 0; mt < 4; mt++) {
#pragma unroll
        for (int nt = 0; nt < 4; nt++) {
            int ml = wm * 64 + mt * 16 + g;
            int nl = wn * 32 + nt * 8 + tg * 2;
#pragma unroll
            for (int half = 0; half < 2; half++) {
                int row = ml + half * 8;
                float v0 = c[mt][nt][half * 2 + 0];
                float v1 = c[mt][nt][half * 2 + 1];
                if (MODE <= 1) {
                    *(float2*)(Cout + (size_t)(m0 + row) * 256 + n0 + nl) =
                        make_float2(v0, v1);
                } else if (MODE == 2) {
                    int t = s_tok[row];
                    if (t >= 0) {
                        float gate = s_gate[row];
                        const float* bb = eb + e * 256 + n0 + nl;
                        float o0 = gate * (v0 + bb[0]);
                        float o1 = gate * (v1 + bb[1]);
                        *(float2*)(Cout + (size_t)s_slot[row] * TT * EE +
                                   (size_t)t * 256 + n0 + nl) = make_float2(o0, o1);
                    }
                } else {
                    if (row < PP) {
#pragma unroll
                        for (int j = 0; j < 2; j++) {
                            int col = nl + j;
                            if (col < NN) {
                                size_t off = (size_t)bz * PP * NN + (size_t)row * NN + col;
                                float s = (j ? v1 : v0) + bias[off] + bias1[off];
                                s = 10.f * tanhf(s * 0.0625f);
                                Cout[off] = s + ninf[off];
                            }
                        }
                    }
                }
            }
        }
    }
}

// ============================================================
// Attention: block (b,h), 128 threads, thread-per-query-row.
// ============================================================
__global__ __launch_bounds__(128)
void attn_kernel(const float* __restrict__ q,
                 const float* __restrict__ k,
                 const float* __restrict__ v,
                 const float* __restrict__ ninf,
                 float* __restrict__ outc)
{
    extern __shared__ float sm[];
    float* sS = sm;                  // 10100
    float* sK = sm + 10100;          // 1616
    float* sV = sm + 10100 + 1616;   // 1616
    const int b = blockIdx.x, h = blockIdx.y;
    const int tid = threadIdx.x;

    const float4* nf4 = (const float4*)(ninf + (size_t)b * PP * NN);
    float4* sS4 = (float4*)sS;
    for (int i = tid; i < PP * NN / 4; i += 128) sS4[i] = nf4[i];

    const float* kb = k + (size_t)b * NN * EE + h * 16;
    const float* vb = v + (size_t)b * NN * EE + h * 16;
    for (int i = tid; i < NN * 4; i += 128) {
        int n = i >> 2, c = i & 3;
        *(float4*)(sK + n * 16 + c * 4) = *(const float4*)(kb + (size_t)n * EE + c * 4);
        *(float4*)(sV + n * 16 + c * 4) = *(const float4*)(vb + (size_t)n * EE + c * 4);
    }
    __syncthreads();

    if (tid < PP) {
        const int p = tid;
        const float* qb = q + ((size_t)b * PP + p) * EE + h * 16;
        float4 q0 = *(const float4*)(qb);
        float4 q1 = *(const float4*)(qb + 4);
        float4 q2 = *(const float4*)(qb + 8);
        float4 q3 = *(const float4*)(qb + 12);
        float* row = sS + p * NN;

        float mx = -1e30f;
        for (int n = 0; n < NN; n++) {
            const float4* kk4 = (const float4*)(sK + n * 16);
            float4 k0 = kk4[0], k1 = kk4[1], k2 = kk4[2], k3 = kk4[3];
            float s0 = q0.x * k0.x + q0.y * k0.y + q0.z * k0.z + q0.w * k0.w;
            float s1 = q1.x * k1.x + q1.y * k1.y + q1.z * k1.z + q1.w * k1.w;
            float s2 = q2.x * k2.x + q2.y * k2.y + q2.z * k2.z + q2.w * k2.w;
            float s3 = q3.x * k3.x + q3.y * k3.y + q3.z * k3.z + q3.w * k3.w;
            float sc = (s0 + s1 + s2 + s3) * 0.25f + row[n];
            row[n] = sc;
            mx = fmaxf(mx, sc);
        }
        float sum = 0.f;
        for (int n = 0; n < NN; n++) {
            float e = __expf(row[n] - mx);
            row[n] = e;
            sum += e;
        }
        float inv = 1.f / sum;

        float4 o0 = {0,0,0,0}, o1 = {0,0,0,0}, o2 = {0,0,0,0}, o3 = {0,0,0,0};
        for (int n = 0; n < NN; n++) {
            float w = row[n];
            const float4* vv4 = (const float4*)(sV + n * 16);
            float4 v0 = vv4[0], v1 = vv4[1], v2 = vv4[2], v3 = vv4[3];
            o0.x += w * v0.x; o0.y += w * v0.y; o0.z += w * v0.z; o0.w += w * v0.w;
            o1.x += w * v1.x; o1.y += w * v1.y; o1.z += w * v1.z; o1.w += w * v1.w;
            o2.x += w * v2.x; o2.y += w * v2.y; o2.z += w * v2.z; o2.w += w * v2.w;
            o3.x += w * v3.x; o3.y += w * v3.y; o3.z += w * v3.z; o3.w += w * v3.w;
        }
        float* ob = outc + ((size_t)b * PP + p) * EE + h * 16;
        o0.x *= inv; o0.y *= inv; o0.z *= inv; o0.w *= inv;
        o1.x *= inv; o1.y *= inv; o1.z *= inv; o1.w *= inv;
        o2.x *= inv; o2.y *= inv; o2.z *= inv; o2.w *= inv;
        o3.x *= inv; o3.y *= inv; o3.z *= inv; o3.w *= inv;
        ((float4*)ob)[0] = o0; ((float4*)ob)[1] = o1;
        ((float4*)ob)[2] = o2; ((float4*)ob)[3] = o3;
    }
}

// ============================================================
// Routing: warp per token -> top2 of x@Wg + gate softmax
// ============================================================
__global__ void route_kernel(const float* __restrict__ x,
                             const float* __restrict__ Wg,
                             int* __restrict__ topi,
                             float* __restrict__ topg)
{
    const int wid = threadIdx.x >> 5, lane = threadIdx.x & 31;
    const int t = blockIdx.x * 8 + wid;
    if (t >= TT) return;
    float lg[8];
#pragma unroll
    for (int e = 0; e < 8; e++) lg[e] = 0.f;
    for (int f = lane; f < 256; f += 32) {
        float xv = x[(size_t)t * 256 + f];
        const float4* wg4 = (const float4*)&Wg[f * 8];
        float4 w0 = wg4[0], w1 = wg4[1];
        lg[0] += xv * w0.x; lg[1] += xv * w0.y; lg[2] += xv * w0.z; lg[3] += xv * w0.w;
        lg[4] += xv * w1.x; lg[5] += xv * w1.y; lg[6] += xv * w1.z; lg[7] += xv * w1.w;
    }
#pragma unroll
    for (int e = 0; e < 8; e++)
#pragma unroll
        for (int o = 16; o; o >>= 1) lg[e] += __shfl_xor_sync(~0u, lg[e], o);
    if (lane == 0) {
        float v1 = -1e30f, v2 = -1e30f; int i1 = 0, i2 = 0;
#pragma unroll
        for (int e = 0; e < 8; e++) {
            float vv = lg[e];
            if (vv > v1) { v2 = v1; i2 = i1; v1 = vv; i1 = e; }
            else if (vv > v2) { v2 = vv; i2 = e; }
        }
        float ex = expf(v2 - v1);
        float g1 = 1.f / (1.f + ex);
        topi[2 * t] = i1;  topi[2 * t + 1] = i2;
        topg[2 * t] = g1;  topg[2 * t + 1] = ex * g1;
    }
}

// ============================================================
// Per-expert token list via ballot scan (deterministic)
// ============================================================
__global__ void build_lists_kernel(const int* __restrict__ topi,
                                   int* __restrict__ list,
                                   int* __restrict__ count)
{
    const int e = blockIdx.x;
    const int tid = threadIdx.x;
    const int wid = tid >> 5, lane = tid & 31;
    __shared__ int wtot[8];
    __shared__ int base;
    if (tid == 0) base = 0;
    __syncthreads();
    for (int c = 0; c < TT / 256; c++) {
        int t = c * 256 + tid;
        int slot = -1;
        int a = topi[2 * t], bq = topi[2 * t + 1];
        if (a == e) slot = 0; else if (bq == e) slot = 1;
        unsigned mask = __ballot_sync(0xffffffffu, slot >= 0);
        int wpre = __popc(mask & ((1u << lane) - 1));
        if (lane == 0) wtot[wid] = __popc(mask);
        __syncthreads();
        int wbase = 0, ctot = 0;
#pragma unroll
        for (int w = 0; w < 8; w++) {
            if (w < wid) wbase += wtot[w];
            ctot += wtot[w];
        }
        if (slot >= 0) list[e * TT + base + wbase + wpre] = t * 2 + slot;
        __syncthreads();
        if (tid == 0) base += ctot;
        __syncthreads();
    }
    if (tid == 0) count[e] = base;
}

// ============================================================
// Output softmax: warp per row over g_s2
// ============================================================
__global__ void softmax_out_kernel(const float* __restrict__ s2,
                                   float* __restrict__ out)
{
    const int wid = threadIdx.x >> 5, lane = threadIdx.x & 31;
    const int r = blockIdx.x * 8 + wid;
    if (r >= TT) return;
    const float* row = s2 + (size_t)r * NN;
    float vals[4];
    float mx = -1e30f;
#pragma unroll
    for (int i = 0; i < 4; i++) {
        int n = lane + i * 32;
        vals[i] = (n < NN) ? row[n] : -1e30f;
        mx = fmaxf(mx, vals[i]);
    }
#pragma unroll
    for (int o = 16; o; o >>= 1) mx = fmaxf(mx, __shfl_xor_sync(~0u, mx, o));
    float sum = 0.f;
#pragma unroll
    for (int i = 0; i < 4; i++) {
        vals[i] = __expf(vals[i] - mx);
        sum += vals[i];
    }
#pragma unroll
    for (int o = 16; o; o >>= 1) sum += __shfl_xor_sync(~0u, sum, o);
    float inv = 1.f / sum;
    float* orow = out + (size_t)r * NN;
#pragma unroll
    for (int i = 0; i < 4; i++) {
        int n = lane + i * 32;
        if (n < NN) orow[n] = vals[i] * inv;
    }
}

// ============================================================
// Host launcher
// ============================================================
extern "C" void kernel_launch(void* const* d_in, const int* in_sizes, int n_in,
                              void* d_out, int out_size)
{
    const float* eln   = (const float*)d_in[0];
    const float* attr  = (const float*)d_in[1];
    const float* enc   = (const float*)d_in[2];
    const float* ninf  = (const float*)d_in[3];
    const float* bias  = (const float*)d_in[4];
    const float* bias1 = (const float*)d_in[5];
    const float* Wq    = (const float*)d_in[6];
    const float* Wk    = (const float*)d_in[7];
    const float* Wv    = (const float*)d_in[8];
    const float* Wg    = (const float*)d_in[9];
    const float* eW    = (const float*)d_in[10];
    const float* eb    = (const float*)d_in[11];
    float* out = (float*)d_out;

    float *pq, *pk, *pv, *patt, *pmh, *ptopg, *ps2;
    int *ptopi, *plist, *pcount;
    cudaGetSymbolAddress((void**)&pq,    g_q);
    cudaGetSymbolAddress((void**)&pk,    g_k);
    cudaGetSymbolAddress((void**)&pv,    g_v);
    cudaGetSymbolAddress((void**)&patt,  g_att);
    cudaGetSymbolAddress((void**)&pmh,   g_mh);
    cudaGetSymbolAddress((void**)&ps2,   g_s2);
    cudaGetSymbolAddress((void**)&ptopi, g_topi);
    cudaGetSymbolAddress((void**)&ptopg, g_topg);
    cudaGetSymbolAddress((void**)&plist, g_list);
    cudaGetSymbolAddress((void**)&pcount,g_count);

    const int attn_smem = (PP * NN + 2 * NN * 16) * 4;
    cudaFuncSetAttribute(attn_kernel,
        cudaFuncAttributeMaxDynamicSharedMemorySize, attn_smem);
    cudaFuncSetAttribute(gemm_tf32<0>,
        cudaFuncAttributeMaxDynamicSharedMemorySize, GEMM_SMEM);
    cudaFuncSetAttribute(gemm_tf32<1>,
        cudaFuncAttributeMaxDynamicSharedMemorySize, GEMM_SMEM);
    cudaFuncSetAttribute(gemm_tf32<2>,
        cudaFuncAttributeMaxDynamicSharedMemorySize, GEMM_SMEM);
    cudaFuncSetAttribute(gemm_tf32<3>,
        cudaFuncAttributeMaxDynamicSharedMemorySize, GEMM_SMEM);

    // q/k/v projections (tf32x3)
    gemm_tf32<1><<<dim3(TT / 128, 2, 1), 256, GEMM_SMEM>>>(eln, attr, Wq, pq, TT, 260,
        nullptr, nullptr, nullptr, nullptr, nullptr, nullptr, nullptr);
    gemm_tf32<0><<<dim3(BB * NN / 128, 2, 1), 256, GEMM_SMEM>>>(enc, nullptr, Wk, pk, BB * NN, 256,
        nullptr, nullptr, nullptr, nullptr, nullptr, nullptr, nullptr);
    gemm_tf32<0><<<dim3(BB * NN / 128, 2, 1), 256, GEMM_SMEM>>>(enc, nullptr, Wv, pv, BB * NN, 256,
        nullptr, nullptr, nullptr, nullptr, nullptr, nullptr, nullptr);
    // attention
    attn_kernel<<<dim3(BB, HH), 128, attn_smem>>>(pq, pk, pv, ninf, patt);
    // routing + lists
    route_kernel<<<TT / 8, 256>>>(patt, Wg, ptopi, ptopg);
    build_lists_kernel<<<NE, 256>>>(ptopi, plist, pcount);
    // gathered expert GEMM (tf32x3), gate+bias fused
    gemm_tf32<2><<<dim3(TT / 128, 2, NE), 256, GEMM_SMEM>>>(patt, nullptr, eW, pmh, TT, 256,
        plist, pcount, ptopg, eb, nullptr, nullptr, nullptr);
    // pointer-score GEMM with fused bias/tanh/ninf epilogue
    gemm_tf32<3><<<dim3(1, 1, BB), 256, GEMM_SMEM>>>(pmh, nullptr, enc, ps2, PP, 256,
        nullptr, nullptr, nullptr, nullptr, bias, bias1, ninf);
    // output softmax
    softmax_out_kernel<<<(TT + 7) / 8, 256>>>(ps2, out);
}

// round 4
// speedup vs baseline: 4.0836x; 1.6212x over previous
#include <cuda_runtime.h>
#include <cuda_bf16.h>
#include <cstdint>
#include <cstddef>

// ---------------- problem constants ----------------
#define BB   256
#define PP   100
#define NN   101
#define EE   256
#define HH   16
#define NE   8
#define TT   (BB*PP)

// ---------------- scratch ----------------
__device__ float g_q  [TT    * EE];
__device__ float g_k  [BB*NN * EE];
__device__ float g_v  [BB*NN * EE];
__device__ float g_att[TT    * EE];
__device__ float g_mh [2*TT  * EE];
__device__ float g_s2 [BB*PP * NN];
__device__ int   g_topi[TT * 2];
__device__ float g_topg[TT * 2];
__device__ int   g_list[NE * TT];
__device__ int   g_count[NE];

// ---------------- bf16 split helpers ----------------
__device__ __forceinline__ void splitpack(float x0, float x1,
                                          uint32_t& h, uint32_t& l)
{
    __nv_bfloat162 hb = __floats2bfloat162_rn(x0, x1);
    float r0 = x0 - __bfloat162float(hb.x);
    float r1 = x1 - __bfloat162float(hb.y);
    __nv_bfloat162 lb = __floats2bfloat162_rn(r0, r1);
    h = *reinterpret_cast<uint32_t*>(&hb);
    l = *reinterpret_cast<uint32_t*>(&lb);
}
__device__ __forceinline__ void mma16(float c[4],
    uint32_t a0, uint32_t a1, uint32_t a2, uint32_t a3,
    uint32_t b0, uint32_t b1)
{
    asm volatile(
        "mma.sync.aligned.m16n8k16.row.col.f32.bf16.bf16.f32 "
        "{%0,%1,%2,%3}, {%4,%5,%6,%7}, {%8,%9}, {%0,%1,%2,%3};"
        : "+f"(c[0]), "+f"(c[1]), "+f"(c[2]), "+f"(c[3])
        : "r"(a0), "r"(a1), "r"(a2), "r"(a3), "r"(b0), "r"(b1));
}

// ============================================================
// bf16x3 GEMM: 128x128 tile, BK=16, 256 threads (8 warps 2x4),
// warp tile 64x32. smem planes hold packed bf16 pairs (uint32 =
// {k,k+1}) pitch 12 -> conflict-free mma reads. 2-stage double
// buffer.
// MODE 0: fused k/v proj: y<2 -> Wk->g_k, y>=2 -> Wv->g_v
// MODE 1: q proj, A = concat(eln, attr), K=260
// MODE 2: gathered expert GEMM + gate/bias epilogue
// MODE 3: per-batch pointer scores + bias/tanh/ninf epilogue
// ============================================================
#define PLANE 1536               // 128 rows * 12 uint32
#define GEMM_SMEM (8 * PLANE * 4 + 1536)

template<int MODE>
__launch_bounds__(256, 2)
__global__ void gemm_bf16(const float* __restrict__ A,
                          const float* __restrict__ A2,
                          const float* __restrict__ Bm,
                          const float* __restrict__ Bm2,
                          float* __restrict__ Cout,
                          float* __restrict__ Cout2,
                          int M, int K,
                          const int*   __restrict__ list,
                          const int*   __restrict__ count,
                          const float* __restrict__ topg,
                          const float* __restrict__ eb,
                          const float* __restrict__ bias,
                          const float* __restrict__ bias1,
                          const float* __restrict__ ninf)
{
    extern __shared__ uint32_t smemu[];
    uint32_t* Ah = smemu;                // 2 stages x PLANE
    uint32_t* Al = Ah + 2 * PLANE;
    uint32_t* Bh = Al + 2 * PLANE;
    uint32_t* Bl = Bh + 2 * PLANE;
    int*    s_tok  = (int*)  (Bl + 2 * PLANE);
    float*  s_gate = (float*)(s_tok + 128);
    int*    s_slot = (int*)  (s_gate + 128);

    const int tid = threadIdx.x;
    const int m0 = blockIdx.x * 128;
    const int bz = blockIdx.z;

    int n0;
    const float* Aro = A;
    const float* Bro;
    float* Co;
    int e = 0;

    if (MODE == 0) {
        int y = blockIdx.y;
        Bro = (y < 2) ? Bm : Bm2;
        Co  = (y < 2) ? Cout : Cout2;
        n0  = (y & 1) * 128;
    } else {
        Bro = Bm; Co = Cout;
        n0 = blockIdx.y * 128;
    }
    if (MODE == 2) {
        e = bz;
        int cnt = count[e];
        if (m0 >= cnt) return;
        Bro = Bm + (size_t)e * 65536;
        if (tid < 128) {
            int r = m0 + tid;
            if (r < cnt) {
                int entry = list[e * TT + r];
                s_tok[tid]  = entry >> 1;
                s_slot[tid] = entry & 1;
                s_gate[tid] = topg[entry];
            } else s_tok[tid] = -1;
        }
        __syncthreads();
    }
    if (MODE == 3) {
        Aro = A  + (size_t)bz * PP * EE;
        Bro = Bm + (size_t)bz * NN * EE;
    }

    const int NT = (MODE == 1) ? 17 : 16;

    const int wid = tid >> 5, lane = tid & 31;
    const int wm = wid & 1;
    const int wn = wid >> 1;
    const int g  = lane >> 2;
    const int tg = lane & 3;

    // A loader indexing: 2 tasks, each one row m + 4-float k group
    const int amA[2] = { (0*256 + tid) >> 2, (1*256 + tid) >> 2 };
    const int akc    = tid & 3;
    const int akA    = akc * 4;
    // B loader indexing: 2 tasks: n column + 4-k group
    const int bn [2] = { (0*256 + tid) & 127, (1*256 + tid) & 127 };
    const int bkq[2] = { (0*256 + tid) >> 7,  (1*256 + tid) >> 7 };

    float4 av[2], bv[2];

    auto loadA = [&](int k0) {
#pragma unroll
        for (int it = 0; it < 2; it++) {
            int m = amA[it];
            int kg = k0 + akA;
            float4 v = make_float4(0.f, 0.f, 0.f, 0.f);
            if (MODE == 1) {
                if (kg < 256)       v = *(const float4*)(Aro + (size_t)(m0 + m) * 256 + kg);
                else if (kg == 256) v = *(const float4*)(A2 + (size_t)(m0 + m) * 4);
            } else if (MODE == 2) {
                int t = s_tok[m];
                if (t >= 0) v = *(const float4*)(Aro + (size_t)t * 256 + kg);
            } else if (MODE == 3) {
                if (m < PP) {
                    float4 x = *(const float4*)(Aro + (size_t)m * 256 + kg);
                    float4 y = *(const float4*)(Aro + (size_t)TT * EE + (size_t)m * 256 + kg);
                    v = make_float4(x.x + y.x, x.y + y.y, x.z + y.z, x.w + y.w);
                }
            } else {
                v = *(const float4*)(Aro + (size_t)(m0 + m) * 256 + kg);
            }
            av[it] = v;
        }
    };
    auto loadB = [&](int k0) {
#pragma unroll
        for (int it = 0; it < 2; it++) {
            int n = bn[it], kq = bkq[it];
            if (MODE == 3) {
                bv[it] = (n < NN)
                    ? *(const float4*)(Bro + (size_t)n * 256 + k0 + kq * 4)
                    : make_float4(0.f, 0.f, 0.f, 0.f);
            } else {
                float vv[4];
#pragma unroll
                for (int i = 0; i < 4; i++) {
                    int kg = k0 + kq * 4 + i;
                    vv[i] = (kg < K) ? Bro[(size_t)kg * 256 + n0 + n] : 0.f;
                }
                bv[it] = make_float4(vv[0], vv[1], vv[2], vv[3]);
            }
        }
    };
    auto storeTile = [&](int stg) {
        uint32_t* Ahs = Ah + stg * PLANE;
        uint32_t* Als = Al + stg * PLANE;
        uint32_t* Bhs = Bh + stg * PLANE;
        uint32_t* Bls = Bl + stg * PLANE;
#pragma unroll
        for (int it = 0; it < 2; it++) {
            uint32_t h01, l01, h23, l23;
            splitpack(av[it].x, av[it].y, h01, l01);
            splitpack(av[it].z, av[it].w, h23, l23);
            int idx = amA[it] * 12 + akc * 2;
            *(uint2*)&Ahs[idx] = make_uint2(h01, h23);
            *(uint2*)&Als[idx] = make_uint2(l01, l23);
        }
#pragma unroll
        for (int it = 0; it < 2; it++) {
            uint32_t h01, l01, h23, l23;
            splitpack(bv[it].x, bv[it].y, h01, l01);
            splitpack(bv[it].z, bv[it].w, h23, l23);
            int idx = bn[it] * 12 + bkq[it] * 2;
            *(uint2*)&Bhs[idx] = make_uint2(h01, h23);
            *(uint2*)&Bls[idx] = make_uint2(l01, l23);
        }
    };

    float c[4][4][4];
#pragma unroll
    for (int mt = 0; mt < 4; mt++)
#pragma unroll
        for (int nt = 0; nt < 4; nt++)
#pragma unroll
            for (int j = 0; j < 4; j++) c[mt][nt][j] = 0.f;

    loadA(0); loadB(0);
    storeTile(0);
    __syncthreads();

    int cur = 0;
    for (int t = 0; t < NT; t++) {
        if (t + 1 < NT) { loadA((t + 1) * 16); loadB((t + 1) * 16); }

        const uint32_t* Ach = Ah + cur * PLANE;
        const uint32_t* Acl = Al + cur * PLANE;
        const uint32_t* Bch = Bh + cur * PLANE;
        const uint32_t* Bcl = Bl + cur * PLANE;

        uint32_t bhf[4][2], blf[4][2];
#pragma unroll
        for (int nt = 0; nt < 4; nt++) {
            int n = wn * 32 + nt * 8 + g;
            bhf[nt][0] = Bch[n * 12 + tg];
            bhf[nt][1] = Bch[n * 12 + tg + 4];
            blf[nt][0] = Bcl[n * 12 + tg];
            blf[nt][1] = Bcl[n * 12 + tg + 4];
        }
#pragma unroll
        for (int mt = 0; mt < 4; mt++) {
            int r0 = (wm * 64 + mt * 16 + g) * 12;
            int r1 = r0 + 8 * 12;
            uint32_t ah0 = Ach[r0 + tg],     ah1 = Ach[r1 + tg];
            uint32_t ah2 = Ach[r0 + tg + 4], ah3 = Ach[r1 + tg + 4];
            uint32_t al0 = Acl[r0 + tg],     al1 = Acl[r1 + tg];
            uint32_t al2 = Acl[r0 + tg + 4], al3 = Acl[r1 + tg + 4];
#pragma unroll
            for (int nt = 0; nt < 4; nt++) {
                mma16(c[mt][nt], ah0, ah1, ah2, ah3, bhf[nt][0], bhf[nt][1]);
                mma16(c[mt][nt], al0, al1, al2, al3, bhf[nt][0], bhf[nt][1]);
                mma16(c[mt][nt], ah0, ah1, ah2, ah3, blf[nt][0], blf[nt][1]);
            }
        }
        if (t + 1 < NT) {
            storeTile(cur ^ 1);
            __syncthreads();
            cur ^= 1;
        }
    }

    // ---------- epilogue ----------
#pragma unroll
    for (int mt = 0; mt < 4; mt++) {
#pragma unroll
        for (int nt = 0; nt < 4; nt++) {
            int ml = wm * 64 + mt * 16 + g;
            int nl = wn * 32 + nt * 8 + tg * 2;
#pragma unroll
            for (int half = 0; half < 2; half++) {
                int row = ml + half * 8;
                float v0 = c[mt][nt][half * 2 + 0];
                float v1 = c[mt][nt][half * 2 + 1];
                if (MODE <= 1) {
                    *(float2*)(Co + (size_t)(m0 + row) * 256 + n0 + nl) =
                        make_float2(v0, v1);
                } else if (MODE == 2) {
                    int t = s_tok[row];
                    if (t >= 0) {
                        float gate = s_gate[row];
                        const float* bb = eb + e * 256 + n0 + nl;
                        *(float2*)(Co + (size_t)s_slot[row] * TT * EE +
                                   (size_t)t * 256 + n0 + nl) =
                            make_float2(gate * (v0 + bb[0]), gate * (v1 + bb[1]));
                    }
                } else {
                    if (row < PP) {
#pragma unroll
                        for (int j = 0; j < 2; j++) {
                            int col = nl + j;
                            if (col < NN) {
                                size_t off = (size_t)bz * PP * NN + (size_t)row * NN + col;
                                float s = (j ? v1 : v0) + bias[off] + bias1[off];
                                s = 10.f * tanhf(s * 0.0625f);
                                Co[off] = s + ninf[off];
                            }
                        }
                    }
                }
            }
        }
    }
}

// ============================================================
// Attention: block (b,h), 256 threads, 2 threads per query row
// (pair splits the 101-long n loop; combine via shfl_xor 1).
// ============================================================
__global__ __launch_bounds__(256)
void attn_kernel(const float* __restrict__ q,
                 const float* __restrict__ k,
                 const float* __restrict__ v,
                 const float* __restrict__ ninf,
                 float* __restrict__ outc)
{
    extern __shared__ float sm[];
    float* sS = sm;                  // 10100
    float* sK = sm + 10100;          // 1616
    float* sV = sm + 10100 + 1616;   // 1616
    const int b = blockIdx.x, h = blockIdx.y;
    const int tid = threadIdx.x;

    const float4* nf4 = (const float4*)(ninf + (size_t)b * PP * NN);
    float4* sS4 = (float4*)sS;
    for (int i = tid; i < PP * NN / 4; i += 256) sS4[i] = nf4[i];

    const float* kb = k + (size_t)b * NN * EE + h * 16;
    const float* vb = v + (size_t)b * NN * EE + h * 16;
    for (int i = tid; i < NN * 4; i += 256) {
        int n = i >> 2, c = i & 3;
        *(float4*)(sK + n * 16 + c * 4) = *(const float4*)(kb + (size_t)n * EE + c * 4);
        *(float4*)(sV + n * 16 + c * 4) = *(const float4*)(vb + (size_t)n * EE + c * 4);
    }
    __syncthreads();

    const int p = tid >> 1, half = tid & 1;
    if (p < PP) {
        unsigned am = __activemask();
        // each lane of the pair loads 8 of the 16 q floats, exchange by shfl
        const float* qb = q + ((size_t)b * PP + p) * EE + h * 16 + half * 8;
        float4 e0 = *(const float4*)(qb);
        float4 e1 = *(const float4*)(qb + 4);
        float4 f0, f1;
        f0.x = __shfl_xor_sync(am, e0.x, 1); f0.y = __shfl_xor_sync(am, e0.y, 1);
        f0.z = __shfl_xor_sync(am, e0.z, 1); f0.w = __shfl_xor_sync(am, e0.w, 1);
        f1.x = __shfl_xor_sync(am, e1.x, 1); f1.y = __shfl_xor_sync(am, e1.y, 1);
        f1.z = __shfl_xor_sync(am, e1.z, 1); f1.w = __shfl_xor_sync(am, e1.w, 1);
        float4 q0 = half ? f0 : e0;
        float4 q1 = half ? f1 : e1;
        float4 q2 = half ? e0 : f0;
        float4 q3 = half ? e1 : f1;

        const int nbeg = half ? 51 : 0;
        const int nend = half ? NN : 51;
        float* row = sS + p * NN;

        float mx = -1e30f;
        for (int n = nbeg; n < nend; n++) {
            const float4* kk4 = (const float4*)(sK + n * 16);
            float4 k0 = kk4[0], k1 = kk4[1], k2 = kk4[2], k3 = kk4[3];
            float s0 = q0.x * k0.x + q0.y * k0.y + q0.z * k0.z + q0.w * k0.w;
            float s1 = q1.x * k1.x + q1.y * k1.y + q1.z * k1.z + q1.w * k1.w;
            float s2 = q2.x * k2.x + q2.y * k2.y + q2.z * k2.z + q2.w * k2.w;
            float s3 = q3.x * k3.x + q3.y * k3.y + q3.z * k3.z + q3.w * k3.w;
            float sc = (s0 + s1 + s2 + s3) * 0.25f + row[n];
            row[n] = sc;
            mx = fmaxf(mx, sc);
        }
        mx = fmaxf(mx, __shfl_xor_sync(am, mx, 1));

        float sum = 0.f;
        for (int n = nbeg; n < nend; n++) {
            float e = __expf(row[n] - mx);
            row[n] = e;
            sum += e;
        }
        sum += __shfl_xor_sync(am, sum, 1);
        float inv = 1.f / sum;

        float4 o0 = {0,0,0,0}, o1 = {0,0,0,0}, o2 = {0,0,0,0}, o3 = {0,0,0,0};
        for (int n = nbeg; n < nend; n++) {
            float w = row[n];
            const float4* vv4 = (const float4*)(sV + n * 16);
            float4 v0 = vv4[0], v1 = vv4[1], v2 = vv4[2], v3 = vv4[3];
            o0.x += w * v0.x; o0.y += w * v0.y; o0.z += w * v0.z; o0.w += w * v0.w;
            o1.x += w * v1.x; o1.y += w * v1.y; o1.z += w * v1.z; o1.w += w * v1.w;
            o2.x += w * v2.x; o2.y += w * v2.y; o2.z += w * v2.z; o2.w += w * v2.w;
            o3.x += w * v3.x; o3.y += w * v3.y; o3.z += w * v3.z; o3.w += w * v3.w;
        }
        o0.x += __shfl_xor_sync(am, o0.x, 1); o0.y += __shfl_xor_sync(am, o0.y, 1);
        o0.z += __shfl_xor_sync(am, o0.z, 1); o0.w += __shfl_xor_sync(am, o0.w, 1);
        o1.x += __shfl_xor_sync(am, o1.x, 1); o1.y += __shfl_xor_sync(am, o1.y, 1);
        o1.z += __shfl_xor_sync(am, o1.z, 1); o1.w += __shfl_xor_sync(am, o1.w, 1);
        o2.x += __shfl_xor_sync(am, o2.x, 1); o2.y += __shfl_xor_sync(am, o2.y, 1);
        o2.z += __shfl_xor_sync(am, o2.z, 1); o2.w += __shfl_xor_sync(am, o2.w, 1);
        o3.x += __shfl_xor_sync(am, o3.x, 1); o3.y += __shfl_xor_sync(am, o3.y, 1);
        o3.z += __shfl_xor_sync(am, o3.z, 1); o3.w += __shfl_xor_sync(am, o3.w, 1);

        if (half == 0) {
            float* ob = outc + ((size_t)b * PP + p) * EE + h * 16;
            o0.x *= inv; o0.y *= inv; o0.z *= inv; o0.w *= inv;
            o1.x *= inv; o1.y *= inv; o1.z *= inv; o1.w *= inv;
            o2.x *= inv; o2.y *= inv; o2.z *= inv; o2.w *= inv;
            o3.x *= inv; o3.y *= inv; o3.z *= inv; o3.w *= inv;
            ((float4*)ob)[0] = o0; ((float4*)ob)[1] = o1;
            ((float4*)ob)[2] = o2; ((float4*)ob)[3] = o3;
        }
    }
}

// ============================================================
// Routing: warp per token -> top2 of x@Wg + gate softmax
// ============================================================
__global__ void route_kernel(const float* __restrict__ x,
                             const float* __restrict__ Wg,
                             int* __restrict__ topi,
                             float* __restrict__ topg)
{
    const int wid = threadIdx.x >> 5, lane = threadIdx.x & 31;
    const int t = blockIdx.x * 8 + wid;
    if (t >= TT) return;
    float lg[8];
#pragma unroll
    for (int e = 0; e < 8; e++) lg[e] = 0.f;
    for (int f = lane; f < 256; f += 32) {
        float xv = x[(size_t)t * 256 + f];
        const float4* wg4 = (const float4*)&Wg[f * 8];
        float4 w0 = wg4[0], w1 = wg4[1];
        lg[0] += xv * w0.x; lg[1] += xv * w0.y; lg[2] += xv * w0.z; lg[3] += xv * w0.w;
        lg[4] += xv * w1.x; lg[5] += xv * w1.y; lg[6] += xv * w1.z; lg[7] += xv * w1.w;
    }
#pragma unroll
    for (int e = 0; e < 8; e++)
#pragma unroll
        for (int o = 16; o; o >>= 1) lg[e] += __shfl_xor_sync(~0u, lg[e], o);
    if (lane == 0) {
        float v1 = -1e30f, v2 = -1e30f; int i1 = 0, i2 = 0;
#pragma unroll
        for (int e = 0; e < 8; e++) {
            float vv = lg[e];
            if (vv > v1) { v2 = v1; i2 = i1; v1 = vv; i1 = e; }
            else if (vv > v2) { v2 = vv; i2 = e; }
        }
        float ex = expf(v2 - v1);
        float g1 = 1.f / (1.f + ex);
        topi[2 * t] = i1;  topi[2 * t + 1] = i2;
        topg[2 * t] = g1;  topg[2 * t + 1] = ex * g1;
    }
}

// ============================================================
// Per-expert token list via ballot scan (deterministic)
// ============================================================
__global__ void build_lists_kernel(const int* __restrict__ topi,
                                   int* __restrict__ list,
                                   int* __restrict__ count)
{
    const int e = blockIdx.x;
    const int tid = threadIdx.x;
    const int wid = tid >> 5, lane = tid & 31;
    __shared__ int wtot[8];
    __shared__ int base;
    if (tid == 0) base = 0;
    __syncthreads();
    for (int c = 0; c < TT / 256; c++) {
        int t = c * 256 + tid;
        int slot = -1;
        int a = topi[2 * t], bq = topi[2 * t + 1];
        if (a == e) slot = 0; else if (bq == e) slot = 1;
        unsigned mask = __ballot_sync(0xffffffffu, slot >= 0);
        int wpre = __popc(mask & ((1u << lane) - 1));
        if (lane == 0) wtot[wid] = __popc(mask);
        __syncthreads();
        int wbase = 0, ctot = 0;
#pragma unroll
        for (int w = 0; w < 8; w++) {
            if (w < wid) wbase += wtot[w];
            ctot += wtot[w];
        }
        if (slot >= 0) list[e * TT + base + wbase + wpre] = t * 2 + slot;
        __syncthreads();
        if (tid == 0) base += ctot;
        __syncthreads();
    }
    if (tid == 0) count[e] = base;
}

// ============================================================
// Output softmax: warp per row over g_s2
// ============================================================
__global__ void softmax_out_kernel(const float* __restrict__ s2,
                                   float* __restrict__ out)
{
    const int wid = threadIdx.x >> 5, lane = threadIdx.x & 31;
    const int r = blockIdx.x * 8 + wid;
    if (r >= TT) return;
    const float* row = s2 + (size_t)r * NN;
    float vals[4];
    float mx = -1e30f;
#pragma unroll
    for (int i = 0; i < 4; i++) {
        int n = lane + i * 32;
        vals[i] = (n < NN) ? row[n] : -1e30f;
        mx = fmaxf(mx, vals[i]);
    }
#pragma unroll
    for (int o = 16; o; o >>= 1) mx = fmaxf(mx, __shfl_xor_sync(~0u, mx, o));
    float sum = 0.f;
#pragma unroll
    for (int i = 0; i < 4; i++) {
        vals[i] = __expf(vals[i] - mx);
        sum += vals[i];
    }
#pragma unroll
    for (int o = 16; o; o >>= 1) sum += __shfl_xor_sync(~0u, sum, o);
    float inv = 1.f / sum;
    float* orow = out + (size_t)r * NN;
#pragma unroll
    for (int i = 0; i < 4; i++) {
        int n = lane + i * 32;
        if (n < NN) orow[n] = vals[i] * inv;
    }
}

// ============================================================
// Host launcher
// ============================================================
extern "C" void kernel_launch(void* const* d_in, const int* in_sizes, int n_in,
                              void* d_out, int out_size)
{
    const float* eln   = (const float*)d_in[0];
    const float* attr  = (const float*)d_in[1];
    const float* enc   = (const float*)d_in[2];
    const float* ninf  = (const float*)d_in[3];
    const float* bias  = (const float*)d_in[4];
    const float* bias1 = (const float*)d_in[5];
    const float* Wq    = (const float*)d_in[6];
    const float* Wk    = (const float*)d_in[7];
    const float* Wv    = (const float*)d_in[8];
    const float* Wg    = (const float*)d_in[9];
    const float* eW    = (const float*)d_in[10];
    const float* eb    = (const float*)d_in[11];
    float* out = (float*)d_out;

    float *pq, *pk, *pv, *patt, *pmh, *ptopg, *ps2;
    int *ptopi, *plist, *pcount;
    cudaGetSymbolAddress((void**)&pq,    g_q);
    cudaGetSymbolAddress((void**)&pk,    g_k);
    cudaGetSymbolAddress((void**)&pv,    g_v);
    cudaGetSymbolAddress((void**)&patt,  g_att);
    cudaGetSymbolAddress((void**)&pmh,   g_mh);
    cudaGetSymbolAddress((void**)&ps2,   g_s2);
    cudaGetSymbolAddress((void**)&ptopi, g_topi);
    cudaGetSymbolAddress((void**)&ptopg, g_topg);
    cudaGetSymbolAddress((void**)&plist, g_list);
    cudaGetSymbolAddress((void**)&pcount,g_count);

    const int attn_smem = (PP * NN + 2 * NN * 16) * 4;
    cudaFuncSetAttribute(attn_kernel,
        cudaFuncAttributeMaxDynamicSharedMemorySize, attn_smem);
    cudaFuncSetAttribute(gemm_bf16<0>,
        cudaFuncAttributeMaxDynamicSharedMemorySize, GEMM_SMEM);
    cudaFuncSetAttribute(gemm_bf16<1>,
        cudaFuncAttributeMaxDynamicSharedMemorySize, GEMM_SMEM);
    cudaFuncSetAttribute(gemm_bf16<2>,
        cudaFuncAttributeMaxDynamicSharedMemorySize, GEMM_SMEM);
    cudaFuncSetAttribute(gemm_bf16<3>,
        cudaFuncAttributeMaxDynamicSharedMemorySize, GEMM_SMEM);

    // q projection (bf16x3)
    gemm_bf16<1><<<dim3(TT / 128, 2), 256, GEMM_SMEM>>>(
        eln, attr, Wq, nullptr, pq, nullptr, TT, 260,
        nullptr, nullptr, nullptr, nullptr, nullptr, nullptr, nullptr);
    // fused k + v projections
    gemm_bf16<0><<<dim3(BB * NN / 128, 4), 256, GEMM_SMEM>>>(
        enc, nullptr, Wk, Wv, pk, pv, BB * NN, 256,
        nullptr, nullptr, nullptr, nullptr, nullptr, nullptr, nullptr);
    // attention
    attn_kernel<<<dim3(BB, HH), 256, attn_smem>>>(pq, pk, pv, ninf, patt);
    // routing + lists
    route_kernel<<<TT / 8, 256>>>(patt, Wg, ptopi, ptopg);
    build_lists_kernel<<<NE, 256>>>(ptopi, plist, pcount);
    // gathered expert GEMM, gate+bias fused
    gemm_bf16<2><<<dim3(TT / 128, 2, NE), 256, GEMM_SMEM>>>(
        patt, nullptr, eW, nullptr, pmh, nullptr, TT, 256,
        plist, pcount, ptopg, eb, nullptr, nullptr, nullptr);
    // pointer-score GEMM with fused bias/tanh/ninf epilogue
    gemm_bf16<3><<<dim3(1, 1, BB), 256, GEMM_SMEM>>>(
        pmh, nullptr, enc, nullptr, ps2, nullptr, PP, 256,
        nullptr, nullptr, nullptr, nullptr, bias, bias1, ninf);
    // output softmax
    softmax_out_kernel<<<(TT + 7) / 8, 256>>>(ps2, out);
}